// round 2
// baseline (speedup 1.0000x reference)
#include <cuda_runtime.h>
#include <cuda_bf16.h>

#define N_VERTS 100000
#define N_TETS  200000
#define BATCH   64
#define TPB     512                        // tets per block (chunk)
#define NCHUNK  ((N_TETS + TPB - 1) / TPB) // 391
#define THREADS 256

__device__ float g_partial[BATCH * NCHUNK];
__device__ float g_invscale[BATCH];

// ---------------------------------------------------------------------------
// Kernel 1: each block stages 512 tets' int32 indices into smem, then loops
// over all 64 batches, gathers 9 floats per tet, accumulates sum(|det|) with
// a deterministic block reduction into g_partial[b*NCHUNK + chunk].
// All blocks sweep batches in lockstep, so gathers share one 1.2 MB window
// (L2-resident) at a time.
// ---------------------------------------------------------------------------
__global__ void __launch_bounds__(THREADS)
k_det(const float* __restrict__ x, const int* __restrict__ M)
{
    __shared__ int   sIdx[TPB * 3];
    __shared__ float sRed[THREADS / 32];

    const int chunk = blockIdx.x;
    const int tet0  = chunk * TPB;
    const int ntet  = min(TPB, N_TETS - tet0);

    for (int i = threadIdx.x; i < ntet * 3; i += THREADS)
        sIdx[i] = M[tet0 * 3 + i];
    __syncthreads();

    for (int b = 0; b < BATCH; b++) {
        const float* __restrict__ v = x + (size_t)b * (3 * N_VERTS);
        float acc = 0.0f;
        for (int t = threadIdx.x; t < ntet; t += THREADS) {
            const int i0 = sIdx[3*t + 0];
            const int i1 = sIdx[3*t + 1];
            const int i2 = sIdx[3*t + 2];
            // 9 independent gathered loads -> high MLP
            float a0 = __ldg(v + 3*i0 + 0), a1 = __ldg(v + 3*i0 + 1), a2 = __ldg(v + 3*i0 + 2);
            float b0 = __ldg(v + 3*i1 + 0), b1 = __ldg(v + 3*i1 + 1), b2 = __ldg(v + 3*i1 + 2);
            float c0 = __ldg(v + 3*i2 + 0), c1 = __ldg(v + 3*i2 + 1), c2 = __ldg(v + 3*i2 + 2);
            float det = a0 * (b1 * c2 - b2 * c1)
                      - a1 * (b0 * c2 - b2 * c0)
                      + a2 * (b0 * c1 - b1 * c0);
            acc += fabsf(det);
        }
        #pragma unroll
        for (int o = 16; o > 0; o >>= 1)
            acc += __shfl_xor_sync(0xffffffffu, acc, o);
        if ((threadIdx.x & 31) == 0)
            sRed[threadIdx.x >> 5] = acc;
        __syncthreads();
        if (threadIdx.x < 32) {
            float r = (threadIdx.x < (THREADS / 32)) ? sRed[threadIdx.x] : 0.0f;
            #pragma unroll
            for (int o = 4; o > 0; o >>= 1)
                r += __shfl_xor_sync(0xffffffffu, r, o);
            if (threadIdx.x == 0)
                g_partial[b * NCHUNK + chunk] = r;
        }
        __syncthreads();   // protect sRed reuse next batch
    }
}

// ---------------------------------------------------------------------------
// Kernel 2: 64 blocks; block b reduces its NCHUNK partials, computes
// 1 / cbrt(vol/6).
// ---------------------------------------------------------------------------
__global__ void __launch_bounds__(128)
k_finish()
{
    __shared__ float sRed[4];
    const int b = blockIdx.x;
    float acc = 0.0f;
    for (int i = threadIdx.x; i < NCHUNK; i += 128)
        acc += g_partial[b * NCHUNK + i];
    #pragma unroll
    for (int o = 16; o > 0; o >>= 1)
        acc += __shfl_xor_sync(0xffffffffu, acc, o);
    if ((threadIdx.x & 31) == 0)
        sRed[threadIdx.x >> 5] = acc;
    __syncthreads();
    if (threadIdx.x == 0) {
        float vol = (sRed[0] + sRed[1] + sRed[2] + sRed[3]) / 6.0f;
        g_invscale[b] = 1.0f / cbrtf(vol);
    }
}

// ---------------------------------------------------------------------------
// Kernel 3: out = x * invscale[batch], float4-vectorized.
// ---------------------------------------------------------------------------
#define N4_PER_BATCH (3 * N_VERTS / 4)   // 75000
#define N4_TOTAL     (BATCH * N4_PER_BATCH)

__global__ void __launch_bounds__(256)
k_out(const float4* __restrict__ x4, float4* __restrict__ out4)
{
    const long long i = (long long)blockIdx.x * 256 + threadIdx.x;
    if (i < (long long)N4_TOTAL) {
        const int b = (int)(i / N4_PER_BATCH);
        const float s = g_invscale[b];
        float4 v = x4[i];
        v.x *= s; v.y *= s; v.z *= s; v.w *= s;
        out4[i] = v;
    }
}

// ---------------------------------------------------------------------------
extern "C" void kernel_launch(void* const* d_in, const int* in_sizes, int n_in,
                              void* d_out, int out_size)
{
    // Identify inputs by element count to be robust to ordering:
    // x: 64*300000 = 19,200,000 float32 ; M: 200000*3 = 600,000 int32
    const void* p0 = d_in[0];
    const void* p1 = d_in[1];
    const float* x;
    const int*   M;
    if (in_sizes[0] == 19200000) { x = (const float*)p0; M = (const int*)p1; }
    else                         { x = (const float*)p1; M = (const int*)p0; }
    float* o = (float*)d_out;

    k_det<<<NCHUNK, THREADS>>>(x, M);
    k_finish<<<BATCH, 128>>>();
    k_out<<<(N4_TOTAL + 255) / 256, 256>>>((const float4*)x, (float4*)o);
}

// round 3
// speedup vs baseline: 2.8105x; 2.8105x over previous
#include <cuda_runtime.h>
#include <cuda_bf16.h>

#define N_VERTS 100000
#define N_TETS  200000
#define BATCH   64
#define ROWS    (3 * N_VERTS)      // 300000

#define DET_BLOCKS 296             // 2 full waves on 148 SMs
#define DET_THREADS 256            // 8 warps; 16 tets per block-iteration

__device__ float g_xT[(size_t)ROWS * BATCH];          // 76.8 MB scratch (transposed x)
__device__ float g_partial[DET_BLOCKS * BATCH];
__device__ float g_invscale[BATCH];

// ---------------------------------------------------------------------------
// Transpose x[64][300000] -> xT[300000][64]. Tiled, conflict-free, coalesced
// both directions.
// ---------------------------------------------------------------------------
__global__ void __launch_bounds__(256)
k_transpose(const float* __restrict__ x)
{
    __shared__ float tile[64][65];
    const int row0 = blockIdx.x * 64;
    const int tx = threadIdx.x;          // 0..63
    const int ty = threadIdx.y;          // 0..3

    const int r = row0 + tx;
    if (r < ROWS) {
        #pragma unroll
        for (int b = ty; b < BATCH; b += 4)
            tile[tx][b] = x[(size_t)b * ROWS + r];   // coalesced along rows
    }
    __syncthreads();
    #pragma unroll
    for (int rr = ty; rr < 64; rr += 4) {
        const int row = row0 + rr;
        if (row < ROWS)
            g_xT[(size_t)row * BATCH + tx] = tile[rr][tx];  // coalesced along batch
    }
}

// ---------------------------------------------------------------------------
// Det kernel: each warp handles 2 tets x 64 batches per iteration.
// lane = (tetHalf = lane>>4, batchGroup bg = lane&15); each lane computes
// |det| for 4 batches via 9 coalesced float4 loads from xT.
// Deterministic reduction: shfl halves -> per-warp smem -> per-block partial.
// ---------------------------------------------------------------------------
__global__ void __launch_bounds__(DET_THREADS)
k_det(const int* __restrict__ M)
{
    __shared__ float sSum[8][64];

    const int wid  = threadIdx.x >> 5;
    const int lane = threadIdx.x & 31;
    const int half = lane >> 4;          // which of the warp's 2 tets
    const int bg   = lane & 15;          // batch group (4 batches)

    float acc0 = 0.f, acc1 = 0.f, acc2 = 0.f, acc3 = 0.f;
    const float4* __restrict__ xt4 = (const float4*)g_xT;   // row r -> xt4[r*16 + bg]

    #pragma unroll 2
    for (int base = blockIdx.x * 16; base < N_TETS; base += DET_BLOCKS * 16) {
        const int t  = base + wid * 2 + half;
        const int i0 = __ldg(M + 3 * t + 0);
        const int i1 = __ldg(M + 3 * t + 1);
        const int i2 = __ldg(M + 3 * t + 2);

        const float4* pa = xt4 + (size_t)(3 * i0) * 16 + bg;
        const float4* pb = xt4 + (size_t)(3 * i1) * 16 + bg;
        const float4* pc = xt4 + (size_t)(3 * i2) * 16 + bg;

        float4 ax = __ldg(pa), ay = __ldg(pa + 16), az = __ldg(pa + 32);
        float4 bx = __ldg(pb), by = __ldg(pb + 16), bz = __ldg(pb + 32);
        float4 cx = __ldg(pc), cy = __ldg(pc + 16), cz = __ldg(pc + 32);

        acc0 += fabsf(ax.x * (by.x * cz.x - bz.x * cy.x)
                    - ay.x * (bx.x * cz.x - bz.x * cx.x)
                    + az.x * (bx.x * cy.x - by.x * cx.x));
        acc1 += fabsf(ax.y * (by.y * cz.y - bz.y * cy.y)
                    - ay.y * (bx.y * cz.y - bz.y * cx.y)
                    + az.y * (bx.y * cy.y - by.y * cx.y));
        acc2 += fabsf(ax.z * (by.z * cz.z - bz.z * cy.z)
                    - ay.z * (bx.z * cz.z - bz.z * cx.z)
                    + az.z * (bx.z * cy.z - by.z * cx.z));
        acc3 += fabsf(ax.w * (by.w * cz.w - bz.w * cy.w)
                    - ay.w * (bx.w * cz.w - bz.w * cx.w)
                    + az.w * (bx.w * cy.w - by.w * cx.w));
    }

    // combine the warp's two tet-halves (same batches)
    acc0 += __shfl_down_sync(0xffffffffu, acc0, 16);
    acc1 += __shfl_down_sync(0xffffffffu, acc1, 16);
    acc2 += __shfl_down_sync(0xffffffffu, acc2, 16);
    acc3 += __shfl_down_sync(0xffffffffu, acc3, 16);
    if (lane < 16)
        ((float4*)sSum[wid])[bg] = make_float4(acc0, acc1, acc2, acc3);
    __syncthreads();

    if (threadIdx.x < 64) {
        float s = 0.f;
        #pragma unroll
        for (int w = 0; w < 8; w++) s += sSum[w][threadIdx.x];
        g_partial[blockIdx.x * 64 + threadIdx.x] = s;
    }
}

// ---------------------------------------------------------------------------
// Finish: per-batch sum over DET_BLOCKS partials -> 1/cbrt(vol/6).
// ---------------------------------------------------------------------------
__global__ void k_finish()
{
    const int b = threadIdx.x;       // 64 threads
    float s = 0.f;
    #pragma unroll 8
    for (int blk = 0; blk < DET_BLOCKS; blk++)
        s += g_partial[blk * 64 + b];
    g_invscale[b] = 1.0f / cbrtf(s / 6.0f);
}

// ---------------------------------------------------------------------------
// out = x * invscale[batch], float4-vectorized.
// ---------------------------------------------------------------------------
#define N4_PER_BATCH (ROWS / 4)          // 75000
#define N4_TOTAL     (BATCH * N4_PER_BATCH)

__global__ void __launch_bounds__(256)
k_out(const float4* __restrict__ x4, float4* __restrict__ out4)
{
    const long long i = (long long)blockIdx.x * 256 + threadIdx.x;
    if (i < (long long)N4_TOTAL) {
        const int b = (int)(i / N4_PER_BATCH);
        const float s = g_invscale[b];
        float4 v = x4[i];
        v.x *= s; v.y *= s; v.z *= s; v.w *= s;
        out4[i] = v;
    }
}

// ---------------------------------------------------------------------------
extern "C" void kernel_launch(void* const* d_in, const int* in_sizes, int n_in,
                              void* d_out, int out_size)
{
    // x: 19,200,000 float32 ; M: 600,000 int32 — select by element count.
    const float* x;
    const int*   M;
    if (in_sizes[0] == 19200000) { x = (const float*)d_in[0]; M = (const int*)d_in[1]; }
    else                         { x = (const float*)d_in[1]; M = (const int*)d_in[0]; }
    float* o = (float*)d_out;

    k_transpose<<<(ROWS + 63) / 64, dim3(64, 4)>>>(x);
    k_det<<<DET_BLOCKS, DET_THREADS>>>(M);
    k_finish<<<1, 64>>>();
    k_out<<<(N4_TOTAL + 255) / 256, 256>>>((const float4*)x, (float4*)o);
}

// round 4
// speedup vs baseline: 3.5496x; 1.2629x over previous
#include <cuda_runtime.h>
#include <cuda_bf16.h>

#define N_VERTS 100000
#define N_TETS  200000
#define BATCH   64
#define ROWS    (3 * N_VERTS)      // 300000

#define DET_BLOCKS 592             // 4 waves on 148 SMs
#define DET_THREADS 256            // 8 warps; 16 tets per block-iteration

__device__ float g_xT[(size_t)ROWS * BATCH];          // 76.8 MB scratch (transposed x)
__device__ float g_partial[DET_BLOCKS * BATCH];
__device__ float g_invscale[BATCH];
__device__ unsigned g_counter;                        // zero-init, self-resetting

// ---------------------------------------------------------------------------
// Transpose x[64][300000] -> xT[300000][64]. x is read exactly once in the
// whole pipeline (here), so read it evict-first (__ldcs); xT writes stay
// evict-normal so det + out find them in L2.
// ---------------------------------------------------------------------------
__global__ void __launch_bounds__(256)
k_transpose(const float* __restrict__ x)
{
    __shared__ float tile[64][65];
    const int row0 = blockIdx.x * 64;
    const int tx = threadIdx.x & 63;
    const int ty = threadIdx.x >> 6;     // 0..3

    const int r = row0 + tx;
    if (r < ROWS) {
        #pragma unroll
        for (int b = ty; b < BATCH; b += 4)
            tile[tx][b] = __ldcs(x + (size_t)b * ROWS + r);   // coalesced along rows
    }
    __syncthreads();
    #pragma unroll
    for (int rr = ty; rr < 64; rr += 4) {
        const int row = row0 + rr;
        if (row < ROWS)
            g_xT[(size_t)row * BATCH + tx] = tile[rr][tx];    // coalesced along batch
    }
}

// ---------------------------------------------------------------------------
// Det kernel: each warp handles 2 tets x 64 batches per iteration.
// lane = (tetHalf = lane>>4, batchGroup bg = lane&15); each lane computes
// |det| for 4 batches via 9 coalesced float4 loads from xT.
// Last block (fenced atomic ticket) reduces partials -> g_invscale. Fully
// deterministic: fixed summation order, counter resets to 0 each call.
// ---------------------------------------------------------------------------
__global__ void __launch_bounds__(DET_THREADS)
k_det(const int* __restrict__ M)
{
    __shared__ float sSum[8][64];
    __shared__ unsigned sTicket;

    const int wid  = threadIdx.x >> 5;
    const int lane = threadIdx.x & 31;
    const int half = lane >> 4;
    const int bg   = lane & 15;

    float acc0 = 0.f, acc1 = 0.f, acc2 = 0.f, acc3 = 0.f;
    const float4* __restrict__ xt4 = (const float4*)g_xT;   // row r -> xt4[r*16 + bg]

    #pragma unroll 2
    for (int base = blockIdx.x * 16; base < N_TETS; base += DET_BLOCKS * 16) {
        const int t  = base + wid * 2 + half;
        const int i0 = __ldg(M + 3 * t + 0);
        const int i1 = __ldg(M + 3 * t + 1);
        const int i2 = __ldg(M + 3 * t + 2);

        const float4* pa = xt4 + (size_t)(3 * i0) * 16 + bg;
        const float4* pb = xt4 + (size_t)(3 * i1) * 16 + bg;
        const float4* pc = xt4 + (size_t)(3 * i2) * 16 + bg;

        float4 ax = __ldg(pa), ay = __ldg(pa + 16), az = __ldg(pa + 32);
        float4 bx = __ldg(pb), by = __ldg(pb + 16), bz = __ldg(pb + 32);
        float4 cx = __ldg(pc), cy = __ldg(pc + 16), cz = __ldg(pc + 32);

        acc0 += fabsf(ax.x * (by.x * cz.x - bz.x * cy.x)
                    - ay.x * (bx.x * cz.x - bz.x * cx.x)
                    + az.x * (bx.x * cy.x - by.x * cx.x));
        acc1 += fabsf(ax.y * (by.y * cz.y - bz.y * cy.y)
                    - ay.y * (bx.y * cz.y - bz.y * cx.y)
                    + az.y * (bx.y * cy.y - by.y * cx.y));
        acc2 += fabsf(ax.z * (by.z * cz.z - bz.z * cy.z)
                    - ay.z * (bx.z * cz.z - bz.z * cx.z)
                    + az.z * (bx.z * cy.z - by.z * cx.z));
        acc3 += fabsf(ax.w * (by.w * cz.w - bz.w * cy.w)
                    - ay.w * (bx.w * cz.w - bz.w * cx.w)
                    + az.w * (bx.w * cy.w - by.w * cx.w));
    }

    acc0 += __shfl_down_sync(0xffffffffu, acc0, 16);
    acc1 += __shfl_down_sync(0xffffffffu, acc1, 16);
    acc2 += __shfl_down_sync(0xffffffffu, acc2, 16);
    acc3 += __shfl_down_sync(0xffffffffu, acc3, 16);
    if (lane < 16)
        ((float4*)sSum[wid])[bg] = make_float4(acc0, acc1, acc2, acc3);
    __syncthreads();

    if (threadIdx.x < 64) {
        float s = 0.f;
        #pragma unroll
        for (int w = 0; w < 8; w++) s += sSum[w][threadIdx.x];
        g_partial[blockIdx.x * 64 + threadIdx.x] = s;
    }
    __syncthreads();

    if (threadIdx.x == 0) {
        __threadfence();
        sTicket = atomicAdd(&g_counter, 1u);
    }
    __syncthreads();

    if (sTicket == DET_BLOCKS - 1) {           // last block finishes
        __threadfence();                       // acquire partials
        if (threadIdx.x < 64) {
            const volatile float* p = g_partial;
            float s = 0.f;
            for (int blk = 0; blk < DET_BLOCKS; blk++)
                s += p[blk * 64 + threadIdx.x];
            g_invscale[threadIdx.x] = 1.0f / cbrtf(s / 6.0f);
        }
        if (threadIdx.x == 0)
            g_counter = 0;                     // reset for next graph replay
    }
}

// ---------------------------------------------------------------------------
// Output pass: inverse transpose with scale. Reads xT (hot in L2 after det),
// writes out[b][row] coalesced with streaming stores.
// ---------------------------------------------------------------------------
__global__ void __launch_bounds__(256)
k_outT(float* __restrict__ out)
{
    __shared__ float tile[64][65];
    const int row0 = blockIdx.x * 64;
    const int tx = threadIdx.x & 63;
    const int ty = threadIdx.x >> 6;     // 0..3

    const float inv = g_invscale[tx];    // tx = batch in read phase
    #pragma unroll
    for (int rr = ty; rr < 64; rr += 4) {
        const int row = row0 + rr;
        if (row < ROWS)
            tile[rr][tx] = g_xT[(size_t)row * BATCH + tx] * inv;  // coalesced
    }
    __syncthreads();
    const int r = row0 + tx;             // tx = row offset in write phase
    if (r < ROWS) {
        #pragma unroll
        for (int b = ty; b < BATCH; b += 4)
            __stcs(out + (size_t)b * ROWS + r, tile[tx][b]);      // coalesced, streaming
    }
}

// ---------------------------------------------------------------------------
extern "C" void kernel_launch(void* const* d_in, const int* in_sizes, int n_in,
                              void* d_out, int out_size)
{
    // x: 19,200,000 float32 ; M: 600,000 int32 — select by element count.
    const float* x;
    const int*   M;
    if (in_sizes[0] == 19200000) { x = (const float*)d_in[0]; M = (const int*)d_in[1]; }
    else                         { x = (const float*)d_in[1]; M = (const int*)d_in[0]; }
    float* o = (float*)d_out;

    const int tBlocks = (ROWS + 63) / 64;    // 4688
    k_transpose<<<tBlocks, 256>>>(x);
    k_det<<<DET_BLOCKS, DET_THREADS>>>(M);
    k_outT<<<tBlocks, 256>>>(o);
}

// round 5
// speedup vs baseline: 4.2620x; 1.2007x over previous
#include <cuda_runtime.h>
#include <cuda_fp16.h>
#include <cuda_bf16.h>

#define N_VERTS 100000
#define N_TETS  200000
#define BATCH   64
#define ROWS    (3 * N_VERTS)      // 300000

#define DET_BLOCKS 592             // 4 waves on 148 SMs
#define DET_THREADS 256            // 8 warps; 16 tets per block-iteration

__device__ __half g_xTh[(size_t)ROWS * BATCH];        // 38.4 MB fp16 transposed x
__device__ float  g_partial[DET_BLOCKS * BATCH];
__device__ float  g_invscale[BATCH];
__device__ unsigned g_counter;                        // zero-init, self-resetting

// ---------------------------------------------------------------------------
// Transpose x[64][300000] -> xTh[300000][64] (fp16). x reads stay evict-normal
// (k_out re-reads x and can hit L2).
// ---------------------------------------------------------------------------
__global__ void __launch_bounds__(256)
k_transpose(const float* __restrict__ x)
{
    __shared__ float tile[64][65];
    const int row0 = blockIdx.x * 64;
    const int tx = threadIdx.x & 63;
    const int ty = threadIdx.x >> 6;     // 0..3

    const int r = row0 + tx;
    if (r < ROWS) {
        #pragma unroll
        for (int b = ty; b < BATCH; b += 4)
            tile[tx][b] = x[(size_t)b * ROWS + r];    // coalesced along rows
    }
    __syncthreads();

    // write phase: 32 threads per row write half2 (batch pairs) -> 128B/row
    const int bp = threadIdx.x & 31;     // batch pair 0..31
    const int r0 = threadIdx.x >> 5;     // 0..7
    __half2* out2 = (__half2*)g_xTh;
    #pragma unroll
    for (int rr = r0; rr < 64; rr += 8) {
        const int row = row0 + rr;
        if (row < ROWS)
            out2[(size_t)row * 32 + bp] =
                __floats2half2_rn(tile[rr][2*bp], tile[rr][2*bp + 1]);
    }
}

// ---------------------------------------------------------------------------
// fp16 row-group load: 4 batches (8 bytes) -> float4
// ---------------------------------------------------------------------------
__device__ __forceinline__ float4 ldh4(const __half* p)
{
    uint2 u = __ldg((const uint2*)p);
    float2 f0 = __half22float2(*(const __half2*)&u.x);
    float2 f1 = __half22float2(*(const __half2*)&u.y);
    return make_float4(f0.x, f0.y, f1.x, f1.y);
}

// ---------------------------------------------------------------------------
// Det kernel: each warp handles 2 tets x 64 batches per iteration.
// lane = (tetHalf = lane>>4, batchGroup bg = lane&15); each lane computes
// |det| for 4 batches via 9 coalesced 8B loads from xTh. Accumulate fp32.
// Last block (fenced atomic ticket) reduces partials -> g_invscale.
// ---------------------------------------------------------------------------
__global__ void __launch_bounds__(DET_THREADS)
k_det(const int* __restrict__ M)
{
    __shared__ float sSum[8][64];
    __shared__ unsigned sTicket;

    const int wid  = threadIdx.x >> 5;
    const int lane = threadIdx.x & 31;
    const int half = lane >> 4;
    const int bg   = lane & 15;

    float acc0 = 0.f, acc1 = 0.f, acc2 = 0.f, acc3 = 0.f;

    #pragma unroll 2
    for (int base = blockIdx.x * 16; base < N_TETS; base += DET_BLOCKS * 16) {
        const int t  = base + wid * 2 + half;
        const int i0 = __ldg(M + 3 * t + 0);
        const int i1 = __ldg(M + 3 * t + 1);
        const int i2 = __ldg(M + 3 * t + 2);

        const __half* pa = g_xTh + (size_t)(3 * i0) * 64 + bg * 4;
        const __half* pb = g_xTh + (size_t)(3 * i1) * 64 + bg * 4;
        const __half* pc = g_xTh + (size_t)(3 * i2) * 64 + bg * 4;

        float4 ax = ldh4(pa), ay = ldh4(pa + 64), az = ldh4(pa + 128);
        float4 bx = ldh4(pb), by = ldh4(pb + 64), bz = ldh4(pb + 128);
        float4 cx = ldh4(pc), cy = ldh4(pc + 64), cz = ldh4(pc + 128);

        acc0 += fabsf(ax.x * (by.x * cz.x - bz.x * cy.x)
                    - ay.x * (bx.x * cz.x - bz.x * cx.x)
                    + az.x * (bx.x * cy.x - by.x * cx.x));
        acc1 += fabsf(ax.y * (by.y * cz.y - bz.y * cy.y)
                    - ay.y * (bx.y * cz.y - bz.y * cx.y)
                    + az.y * (bx.y * cy.y - by.y * cx.y));
        acc2 += fabsf(ax.z * (by.z * cz.z - bz.z * cy.z)
                    - ay.z * (bx.z * cz.z - bz.z * cx.z)
                    + az.z * (bx.z * cy.z - by.z * cx.z));
        acc3 += fabsf(ax.w * (by.w * cz.w - bz.w * cy.w)
                    - ay.w * (bx.w * cz.w - bz.w * cx.w)
                    + az.w * (bx.w * cy.w - by.w * cx.w));
    }

    acc0 += __shfl_down_sync(0xffffffffu, acc0, 16);
    acc1 += __shfl_down_sync(0xffffffffu, acc1, 16);
    acc2 += __shfl_down_sync(0xffffffffu, acc2, 16);
    acc3 += __shfl_down_sync(0xffffffffu, acc3, 16);
    if (lane < 16)
        ((float4*)sSum[wid])[bg] = make_float4(acc0, acc1, acc2, acc3);
    __syncthreads();

    if (threadIdx.x < 64) {
        float s = 0.f;
        #pragma unroll
        for (int w = 0; w < 8; w++) s += sSum[w][threadIdx.x];
        g_partial[blockIdx.x * 64 + threadIdx.x] = s;
    }
    __syncthreads();

    if (threadIdx.x == 0) {
        __threadfence();
        sTicket = atomicAdd(&g_counter, 1u);
    }
    __syncthreads();

    if (sTicket == DET_BLOCKS - 1) {           // last block finishes
        __threadfence();                       // acquire partials
        if (threadIdx.x < 64) {
            const volatile float* p = g_partial;
            float s = 0.f;
            for (int blk = 0; blk < DET_BLOCKS; blk++)
                s += p[blk * 64 + threadIdx.x];
            g_invscale[threadIdx.x] = 1.0f / cbrtf(s / 6.0f);
        }
        if (threadIdx.x == 0)
            g_counter = 0;                     // reset for next graph replay
    }
}

// ---------------------------------------------------------------------------
// out[b][i] = x[b][i] * invscale[b]; batch via blockIdx.y (no division).
// x is last-use here -> __ldcs; out is write-once -> __stcs.
// ---------------------------------------------------------------------------
#define N4_PER_BATCH (ROWS / 4)          // 75000

__global__ void __launch_bounds__(256)
k_out(const float4* __restrict__ x4, float4* __restrict__ out4)
{
    const int i = blockIdx.x * 256 + threadIdx.x;
    if (i < N4_PER_BATCH) {
        const int b = blockIdx.y;
        const float s = g_invscale[b];
        const size_t idx = (size_t)b * N4_PER_BATCH + i;
        float4 v = __ldcs(x4 + idx);
        v.x *= s; v.y *= s; v.z *= s; v.w *= s;
        __stcs(out4 + idx, v);
    }
}

// ---------------------------------------------------------------------------
extern "C" void kernel_launch(void* const* d_in, const int* in_sizes, int n_in,
                              void* d_out, int out_size)
{
    // x: 19,200,000 float32 ; M: 600,000 int32 — select by element count.
    const float* x;
    const int*   M;
    if (in_sizes[0] == 19200000) { x = (const float*)d_in[0]; M = (const int*)d_in[1]; }
    else                         { x = (const float*)d_in[1]; M = (const int*)d_in[0]; }
    float* o = (float*)d_out;

    k_transpose<<<(ROWS + 63) / 64, 256>>>(x);
    k_det<<<DET_BLOCKS, DET_THREADS>>>(M);
    dim3 og((N4_PER_BATCH + 255) / 256, BATCH);
    k_out<<<og, 256>>>((const float4*)x, (float4*)o);
}

// round 6
// speedup vs baseline: 4.5125x; 1.0588x over previous
#include <cuda_runtime.h>
#include <cuda_fp16.h>
#include <cuda_bf16.h>

#define N_VERTS 100000
#define N_TETS  200000
#define BATCH   64
#define ROWS    (3 * N_VERTS)      // 300000

#define DET_BLOCKS 1184            // 8 CTAs/SM on 148 SMs -> full occupancy
#define DET_THREADS 256            // 8 warps; 16 tets per block-iteration

__device__ __half g_xTh[(size_t)ROWS * BATCH];        // 38.4 MB fp16 transposed x
__device__ float  g_partial[DET_BLOCKS * BATCH];
__device__ float  g_invscale[BATCH];
__device__ unsigned g_counter;                        // zero-init, self-resetting

// ---------------------------------------------------------------------------
// Transpose x[64][300000] -> xTh[300000][64] (fp16).
// Read phase: LDG.128 (each thread grabs 4 consecutive rows of one batch).
// Write phase: per thread 8 scalar LDS -> 8 halves -> one STG.128.
// ---------------------------------------------------------------------------
__global__ void __launch_bounds__(256)
k_transpose(const float* __restrict__ x)
{
    __shared__ float tile[64][65];           // [row][batch]
    const int row0 = blockIdx.x * 64;

    // ---- read: 4 iterations cover 64 batches -------------------------------
    const int tx = threadIdx.x & 15;         // row quad 0..15 (rows 4tx..4tx+3)
    const int bq = threadIdx.x >> 4;         // 0..15
    const int r4 = row0 + 4 * tx;
    #pragma unroll
    for (int j = 0; j < 4; j++) {
        const int b = j * 16 + bq;
        if (r4 < ROWS) {                      // ROWS%4==0: float4 never straddles
            float4 v = *(const float4*)(x + (size_t)b * ROWS + r4);
            tile[4*tx + 0][b] = v.x;
            tile[4*tx + 1][b] = v.y;
            tile[4*tx + 2][b] = v.z;
            tile[4*tx + 3][b] = v.w;
        }
    }
    __syncthreads();

    // ---- write: 2 passes x 32 rows; 8 threads per row, 16B halves each -----
    const int g  = threadIdx.x & 7;          // batch octet 0..7
    const int rr0 = threadIdx.x >> 3;        // 0..31
    #pragma unroll
    for (int p = 0; p < 2; p++) {
        const int rr = rr0 + p * 32;
        const int row = row0 + rr;
        if (row < ROWS) {
            __half h[8];
            #pragma unroll
            for (int k = 0; k < 8; k++)
                h[k] = __float2half_rn(tile[rr][8*g + k]);
            ((uint4*)(g_xTh + (size_t)row * 64))[g] = *(const uint4*)h;
        }
    }
}

// ---------------------------------------------------------------------------
// fp16 row-group load: 4 batches (8 bytes) -> float4
// ---------------------------------------------------------------------------
__device__ __forceinline__ float4 ldh4(const __half* p)
{
    uint2 u = __ldg((const uint2*)p);
    float2 f0 = __half22float2(*(const __half2*)&u.x);
    float2 f1 = __half22float2(*(const __half2*)&u.y);
    return make_float4(f0.x, f0.y, f1.x, f1.y);
}

// ---------------------------------------------------------------------------
// Det kernel: each warp handles 2 tets x 64 batches per iteration.
// lane = (tetHalf = lane>>4, batchGroup bg = lane&15); each lane computes
// |det| for 4 batches via 9 coalesced 8B loads from xTh. Accumulate fp32.
// Last block (fenced atomic ticket) reduces partials -> g_invscale.
// ---------------------------------------------------------------------------
__global__ void __launch_bounds__(DET_THREADS)
k_det(const int* __restrict__ M)
{
    __shared__ float sSum[8][64];
    __shared__ float sQ[4][64];
    __shared__ unsigned sTicket;

    const int wid  = threadIdx.x >> 5;
    const int lane = threadIdx.x & 31;
    const int half = lane >> 4;
    const int bg   = lane & 15;

    float acc0 = 0.f, acc1 = 0.f, acc2 = 0.f, acc3 = 0.f;

    #pragma unroll 2
    for (int base = blockIdx.x * 16; base < N_TETS; base += DET_BLOCKS * 16) {
        const int t  = base + wid * 2 + half;
        const int i0 = __ldg(M + 3 * t + 0);
        const int i1 = __ldg(M + 3 * t + 1);
        const int i2 = __ldg(M + 3 * t + 2);

        const __half* pa = g_xTh + (size_t)(3 * i0) * 64 + bg * 4;
        const __half* pb = g_xTh + (size_t)(3 * i1) * 64 + bg * 4;
        const __half* pc = g_xTh + (size_t)(3 * i2) * 64 + bg * 4;

        float4 ax = ldh4(pa), ay = ldh4(pa + 64), az = ldh4(pa + 128);
        float4 bx = ldh4(pb), by = ldh4(pb + 64), bz = ldh4(pb + 128);
        float4 cx = ldh4(pc), cy = ldh4(pc + 64), cz = ldh4(pc + 128);

        acc0 += fabsf(ax.x * (by.x * cz.x - bz.x * cy.x)
                    - ay.x * (bx.x * cz.x - bz.x * cx.x)
                    + az.x * (bx.x * cy.x - by.x * cx.x));
        acc1 += fabsf(ax.y * (by.y * cz.y - bz.y * cy.y)
                    - ay.y * (bx.y * cz.y - bz.y * cx.y)
                    + az.y * (bx.y * cy.y - by.y * cx.y));
        acc2 += fabsf(ax.z * (by.z * cz.z - bz.z * cy.z)
                    - ay.z * (bx.z * cz.z - bz.z * cx.z)
                    + az.z * (bx.z * cy.z - by.z * cx.z));
        acc3 += fabsf(ax.w * (by.w * cz.w - bz.w * cy.w)
                    - ay.w * (bx.w * cz.w - bz.w * cx.w)
                    + az.w * (bx.w * cy.w - by.w * cx.w));
    }

    acc0 += __shfl_down_sync(0xffffffffu, acc0, 16);
    acc1 += __shfl_down_sync(0xffffffffu, acc1, 16);
    acc2 += __shfl_down_sync(0xffffffffu, acc2, 16);
    acc3 += __shfl_down_sync(0xffffffffu, acc3, 16);
    if (lane < 16)
        ((float4*)sSum[wid])[bg] = make_float4(acc0, acc1, acc2, acc3);
    __syncthreads();

    if (threadIdx.x < 64) {
        float s = 0.f;
        #pragma unroll
        for (int w = 0; w < 8; w++) s += sSum[w][threadIdx.x];
        g_partial[blockIdx.x * 64 + threadIdx.x] = s;
    }
    __syncthreads();

    if (threadIdx.x == 0) {
        __threadfence();
        sTicket = atomicAdd(&g_counter, 1u);
    }
    __syncthreads();

    if (sTicket == DET_BLOCKS - 1) {           // last block finishes
        __threadfence();                       // acquire partials
        // 256 threads: (batch b = tid&63, quarter q = tid>>6) each sums 296
        // partials; thread b then combines the 4 quarters in fixed order.
        {
            const int b = threadIdx.x & 63;
            const int q = threadIdx.x >> 6;    // 0..3
            const volatile float* p = g_partial;
            float s = 0.f;
            const int beg = q * (DET_BLOCKS / 4), end = beg + DET_BLOCKS / 4;
            for (int blk = beg; blk < end; blk++)
                s += p[blk * 64 + b];
            sQ[q][b] = s;
        }
        __syncthreads();
        if (threadIdx.x < 64) {
            float s = ((sQ[0][threadIdx.x] + sQ[1][threadIdx.x])
                     +  sQ[2][threadIdx.x]) + sQ[3][threadIdx.x];
            g_invscale[threadIdx.x] = 1.0f / cbrtf(s / 6.0f);
        }
        if (threadIdx.x == 0)
            g_counter = 0;                     // reset for next graph replay
    }
}

// ---------------------------------------------------------------------------
// out[b][i] = x[b][i] * invscale[b]; batch via blockIdx.y (no division).
// ---------------------------------------------------------------------------
#define N4_PER_BATCH (ROWS / 4)          // 75000

__global__ void __launch_bounds__(256)
k_out(const float4* __restrict__ x4, float4* __restrict__ out4)
{
    const int i = blockIdx.x * 256 + threadIdx.x;
    if (i < N4_PER_BATCH) {
        const int b = blockIdx.y;
        const float s = g_invscale[b];
        const size_t idx = (size_t)b * N4_PER_BATCH + i;
        float4 v = __ldcs(x4 + idx);
        v.x *= s; v.y *= s; v.z *= s; v.w *= s;
        __stcs(out4 + idx, v);
    }
}

// ---------------------------------------------------------------------------
extern "C" void kernel_launch(void* const* d_in, const int* in_sizes, int n_in,
                              void* d_out, int out_size)
{
    // x: 19,200,000 float32 ; M: 600,000 int32 — select by element count.
    const float* x;
    const int*   M;
    if (in_sizes[0] == 19200000) { x = (const float*)d_in[0]; M = (const int*)d_in[1]; }
    else                         { x = (const float*)d_in[1]; M = (const int*)d_in[0]; }
    float* o = (float*)d_out;

    k_transpose<<<(ROWS + 63) / 64, 256>>>(x);
    k_det<<<DET_BLOCKS, DET_THREADS>>>(M);
    dim3 og((N4_PER_BATCH + 255) / 256, BATCH);
    k_out<<<og, 256>>>((const float4*)x, (float4*)o);
}